// round 7
// baseline (speedup 1.0000x reference)
#include <cuda_runtime.h>
#include <cstdint>

// Problem constants (fixed by setup_inputs)
#define BATCH 8
#define H 1024
#define W 1024
#define HW (H*W)
#define TH 512
#define TW 512
#define NCELL (TH*TW)                    // 262144 = 2^18
#define COORDS_ELEMS (BATCH*NCELL*4*2)   // 16777216
#define WEIGHTS_ELEMS (BATCH*NCELL*4)    // 8388608
#define CTILES_PER_IMG 128               // 8 x-tiles (128 wide) * 16 y-tiles (64 tall)
#define NCONTRAST (BATCH*CTILES_PER_IMG) // 1024 contrast blocks
#define CELLS_PER_TFB 2048               // cells per threefry block
#define NTFB (BATCH*NCELL/CELLS_PER_TFB) // 1024 threefry blocks

// Scratch (static device globals — allocation-free per harness rules)
__device__ float g_contrast[BATCH*HW];
__device__ float g_bmn[NCONTRAST];
__device__ float g_bmx[NCONTRAST];

// ---------------------------------------------------------------------------
// JAX threefry2x32, key = jax.random.key(42) -> (0, 42)
// ---------------------------------------------------------------------------
__device__ __forceinline__ unsigned rotl32(unsigned x, int r) {
    return __funnelshift_l(x, x, r);
}

__device__ __forceinline__ void threefry2x32(unsigned x0, unsigned x1,
                                             unsigned& o0, unsigned& o1) {
    const unsigned ks0 = 0u, ks1 = 42u, ks2 = 0x1BD11BF0u;
    x0 += ks0; x1 += ks1;
#define TFR(r) { x0 += x1; x1 = rotl32(x1, r); x1 ^= x0; }
    TFR(13) TFR(15) TFR(26) TFR(6)
    x0 += ks1; x1 += ks2 + 1u;
    TFR(17) TFR(29) TFR(16) TFR(24)
    x0 += ks2; x1 += ks0 + 2u;
    TFR(13) TFR(15) TFR(26) TFR(6)
    x0 += ks0; x1 += ks1 + 3u;
    TFR(17) TFR(29) TFR(16) TFR(24)
    x0 += ks1; x1 += ks2 + 4u;
    TFR(13) TFR(15) TFR(26) TFR(6)
    x0 += ks2; x1 += ks0 + 5u;
#undef TFR
    o0 = x0; o1 = x1;
}

__device__ __forceinline__ float tf_uniform(unsigned flat_idx) {
    unsigned o0, o1;
    threefry2x32(0u, flat_idx, o0, o1);
    unsigned bits = o0 ^ o1;
    return __uint_as_float((bits >> 9) | 0x3f800000u) - 1.0f;
}

// ---------------------------------------------------------------------------
// gray row loader: 8 gray values covering cols x4-2 .. x4+5 of row y
// (zero outside image -> matches zero-padded convs).
// ---------------------------------------------------------------------------
__device__ __forceinline__ void gray_row8(const float* __restrict__ ib,
                                          int y, int x4, float* g8) {
    if ((unsigned)y >= H) {
#pragma unroll
        for (int i = 0; i < 8; ++i) g8[i] = 0.0f;
        return;
    }
    const float* rp = ib + y * W + x4;
    float rr[8], gg[8], bb[8];
#define LOADP(dst, off) { \
        const float* pp = rp + (off); \
        float4 m = *(const float4*)pp; \
        dst[2] = m.x; dst[3] = m.y; dst[4] = m.z; dst[5] = m.w; \
        if (x4 >= 4) { float4 a = *(const float4*)(pp - 4); dst[0] = a.z; dst[1] = a.w; } \
        else { dst[0] = 0.0f; dst[1] = 0.0f; } \
        if (x4 + 4 < W) { float4 c = *(const float4*)(pp + 4); dst[6] = c.x; dst[7] = c.y; } \
        else { dst[6] = 0.0f; dst[7] = 0.0f; } }
    LOADP(rr, 0)
    LOADP(gg, HW)
    LOADP(bb, 2 * HW)
#undef LOADP
#pragma unroll
    for (int i = 0; i < 8; ++i)
        g8[i] = rr[i] * 0.299f + gg[i] * 0.587f + bb[i] * 0.114f;
}

// ---------------------------------------------------------------------------
// K1: interleaved fat kernel. Even bid -> contrast tile (register-rolling,
// 128x64, no smem/syncs in mainloop), odd bid -> threefry coords offsets
// (8 cells per thread).
// ---------------------------------------------------------------------------
__global__ void k_main1(const float* __restrict__ img,
                        float* __restrict__ coords) {
    const int bid = blockIdx.x;
    const int lin = threadIdx.x;

    if ((bid & 1) == 0) {
        // ---------------- contrast tile (128 wide x 64 tall) ----------------
        __shared__ float wmn[8], wmx[8];
        const int cid  = bid >> 1;                 // 0..1023
        const int b    = cid >> 7;
        const int tile = cid & (CTILES_PER_IMG - 1);
        const int bx0 = (tile & 7) * 128;
        const int by0 = (tile >> 3) * 64;
        const int tx = lin & 31, ty = lin >> 5;
        const int x4 = bx0 + tx * 4;
        const int ys = by0 + ty * 8;

        const float* ib = img + (size_t)b * 3 * HW;

        float g[5][8];
        gray_row8(ib, ys - 2, x4, g[0]);
        gray_row8(ib, ys - 1, x4, g[1]);
        gray_row8(ib, ys,     x4, g[2]);
        gray_row8(ib, ys + 1, x4, g[3]);

        float cmin = 3.402823466e+38f, cmax = 0.0f;
        float* crow = g_contrast + b * HW + ys * W + x4;

#pragma unroll
        for (int s = 0; s < 8; ++s) {
            const int y = ys + s;
            gray_row8(ib, y + 2, x4, g[(s + 4) % 5]);
            float* rm1 = g[(s + 1) % 5];
            float* rc  = g[(s + 2) % 5];
            float* rp1 = g[(s + 3) % 5];

            float cc[4];
#pragma unroll
            for (int i = 0; i < 4; ++i) {
                const int p = i + 2;
                float a00 = rm1[p-1], a01 = rm1[p], a02 = rm1[p+1];
                float a10 = rc [p-1], a11 = rc [p], a12 = rc [p+1];
                float a20 = rp1[p-1], a21 = rp1[p], a22 = rp1[p+1];

                float gx2 = (a02 - a00) + 2.0f * (a12 - a10) + (a22 - a20);
                float gy2 = (a20 - a00) + 2.0f * (a21 - a01) + (a22 - a02);
                float sobel = sqrtf(gx2 * gx2 + gy2 * gy2 + 1e-8f);
                float lapl  = fabsf(4.0f * a11 - a01 - a10 - a12 - a21);

                float dx = rc[p+1] - rc[p-1];
                if (x4 == 0     && i == 0) dx = rc[4] - rc[2];
                if (x4 == W - 4 && i == 3) dx = rc[5] - rc[3];
                float dy = rp1[p] - rm1[p];
                if (y == 0)     dy = g[(s + 4) % 5][p] - g[(s + 2) % 5][p];
                if (y == H - 1) dy = g[(s + 2) % 5][p] - g[s % 5][p];
                float gradm = sqrtf(dx * dx + dy * dy + 1e-8f);

                cc[i] = 0.5f * sobel + 0.3f * lapl + 0.2f * gradm;
                cmin = fminf(cmin, cc[i]);
                cmax = fmaxf(cmax, cc[i]);
            }
            float4 cv; cv.x = cc[0]; cv.y = cc[1]; cv.z = cc[2]; cv.w = cc[3];
            *(float4*)crow = cv;
            crow += W;
        }

#pragma unroll
        for (int s = 16; s > 0; s >>= 1) {
            cmin = fminf(cmin, __shfl_xor_sync(0xFFFFFFFFu, cmin, s));
            cmax = fmaxf(cmax, __shfl_xor_sync(0xFFFFFFFFu, cmax, s));
        }
        if (tx == 0) { wmn[ty] = cmin; wmx[ty] = cmax; }
        __syncthreads();
        if (lin == 0) {
            float mn = wmn[0], mx = wmx[0];
#pragma unroll
            for (int s = 1; s < 8; ++s) {
                mn = fminf(mn, wmn[s]);
                mx = fmaxf(mx, wmx[s]);
            }
            g_bmn[cid] = mn;
            g_bmx[cid] = mx;
        }
    } else {
        // ---------------- coords offsets (img-independent) ----------------
        const int tb = bid >> 1;                   // 0..1023
        const int base = tb * CELLS_PER_TFB;
        const float CELLSZ = 0.00390625f;          // 2/512 exact

        for (int k = 0; k < 8; ++k) {
            const int t = base + k * 256 + lin;
            const int cell = t & (NCELL - 1);
            const int i = cell >> 9;
            const int j = cell & (TW - 1);

            float by = -1.0f + (float)i * (2.0f / 511.0f);
            float bx = -1.0f + (float)j * (2.0f / 511.0f);

            unsigned ctr = (unsigned)t * 8u;
            float u[8];
#pragma unroll
            for (int s = 0; s < 8; ++s) u[s] = tf_uniform(ctr + s);

            float4 c0, c1;
            c0.x = by + ((u[0] - 0.5f) * 0.8f) * CELLSZ;
            c0.y = bx + ((u[1] - 0.5f) * 0.8f) * CELLSZ;
            c0.z = by + ((u[2] - 0.5f) * 0.8f) * CELLSZ;
            c0.w = bx + ((u[3] - 0.5f) * 0.8f) * CELLSZ;
            c1.x = by + ((u[4] - 0.5f) * 0.8f) * CELLSZ;
            c1.y = bx + ((u[5] - 0.5f) * 0.8f) * CELLSZ;
            c1.z = by + ((u[6] - 0.5f) * 0.8f) * CELLSZ;
            c1.w = bx + ((u[7] - 0.5f) * 0.8f) * CELLSZ;

            float4* cp = (float4*)coords;
            cp[(size_t)t * 2]     = c0;
            cp[(size_t)t * 2 + 1] = c1;
        }
    }
}

// ---------------------------------------------------------------------------
// horizontal 5-tap of zero-padded contrast at row y, cols x4..x4+3.
// ---------------------------------------------------------------------------
__device__ __forceinline__ float4 hconv(const float* __restrict__ cb,
                                        int y, int x4,
                                        float w0, float w1, float w2,
                                        float w3, float w4) {
    float4 r;
    if ((unsigned)y >= H) { r.x = r.y = r.z = r.w = 0.0f; return r; }
    const float* rp = cb + y * W + x4;
    float f0,f1,f2,f3,f4,f5,f6,f7;
    if (x4 >= 4) {
        float4 a = *(const float4*)(rp - 4);
        f0 = a.z; f1 = a.w;
    } else { f0 = f1 = 0.0f; }
    {
        float4 a = *(const float4*)rp;
        f2 = a.x; f3 = a.y; f4 = a.z; f5 = a.w;
    }
    if (x4 + 4 < W) {
        float4 a = *(const float4*)(rp + 4);
        f6 = a.x; f7 = a.y;
    } else { f6 = f7 = 0.0f; }
    r.x = w0*f0 + w1*f1 + w2*f2 + w3*f3 + w4*f4;
    r.y = w0*f1 + w1*f2 + w2*f3 + w3*f4 + w4*f5;
    r.z = w0*f2 + w1*f3 + w2*f4 + w3*f5 + w4*f6;
    r.w = w0*f3 + w1*f4 + w2*f5 + w3*f6 + w4*f7;
    return r;
}

__device__ __forceinline__ void do_cell(float d, int b, int i, int j,
                                        float* __restrict__ coords,
                                        float* __restrict__ weights) {
    int ns = (d > 0.7f) ? 4 : ((d > 0.4f) ? 2 : 1);
    float wv = d / (float)ns;
    int t = b * NCELL + i * TW + j;
    float4 w4;
    w4.x = wv;
    w4.y = (ns > 1) ? wv : 0.0f;
    w4.z = (ns > 3) ? wv : 0.0f;
    w4.w = (ns > 3) ? wv : 0.0f;
    ((float4*)weights)[t] = w4;
    if (ns == 1) {
        float by = -1.0f + (float)i * (2.0f / 511.0f);
        float bx = -1.0f + (float)j * (2.0f / 511.0f);
        float4 c0; c0.x = by; c0.y = bx; c0.z = by; c0.w = bx;
        float4* cp = (float4*)coords;
        cp[(size_t)t * 2]     = c0;
        cp[(size_t)t * 2 + 1] = c0;
    }
}

// ---------------------------------------------------------------------------
// K2: register-rolling separable gaussian + density + cells.
// Block (32,8) -> 128x64 tile (1024 blocks); thread owns 4 cols x 8 rows.
// ---------------------------------------------------------------------------
__global__ void k_main2(float* __restrict__ dens_out,
                        float* __restrict__ coords,
                        float* __restrict__ weights) {
    __shared__ float rmn[8], rmx[8];

    const int b   = blockIdx.z;
    const int bx0 = blockIdx.x * 128;
    const int by0 = blockIdx.y * 64;
    const int tx = threadIdx.x, ty = threadIdx.y;
    const int lin = ty * 32 + tx;

    // --- batch min/max from per-block results (exact: min/max associative)
    {
        float mn_ = 3.402823466e+38f, mx_ = 0.0f;
        if (lin < CTILES_PER_IMG) {
            mn_ = g_bmn[b * CTILES_PER_IMG + lin];
            mx_ = g_bmx[b * CTILES_PER_IMG + lin];
        }
#pragma unroll
        for (int s = 16; s > 0; s >>= 1) {
            mn_ = fminf(mn_, __shfl_xor_sync(0xFFFFFFFFu, mn_, s));
            mx_ = fmaxf(mx_, __shfl_xor_sync(0xFFFFFFFFu, mx_, s));
        }
        if (tx == 0) { rmn[ty] = mn_; rmx[ty] = mx_; }
    }
    __syncthreads();
    float mn = rmn[0], mx = rmx[0];
#pragma unroll
    for (int s = 1; s < 8; ++s) {
        mn = fminf(mn, rmn[s]);
        mx = fmaxf(mx, rmx[s]);
    }
    const bool ok = mx > mn;
    const float inv = ok ? 1.0f / (mx - mn) : 0.0f;

    // gaussian weights (same fp path as reference)
    const float sg2 = (5.0f / 6.0f) * (5.0f / 6.0f);
    const float e1 = expf(-0.5f / sg2);
    const float e2 = expf(-2.0f / sg2);
    const float ksum = 1.0f + 2.0f * e1 + 2.0f * e2;
    float w[5];
    w[0] = e2 / ksum; w[1] = e1 / ksum; w[2] = 1.0f / ksum; w[3] = w[1]; w[4] = w[0];
    const float w0 = w[0], w1 = w[1], w2 = w[2], w3 = w[3], w4 = w[4];
    const float wsum = ((((w[0] + w[1]) + w[2]) + w[3]) + w[4]);

    const int x4 = bx0 + tx * 4;

    float wxv0 = 0.f, wxv1 = 0.f, wxv2 = 0.f, wxv3 = 0.f;
#pragma unroll
    for (int d = 0; d < 5; ++d) {
        if ((unsigned)(x4 + 0 + d - 2) < W) wxv0 += w[d];
        if ((unsigned)(x4 + 1 + d - 2) < W) wxv1 += w[d];
        if ((unsigned)(x4 + 2 + d - 2) < W) wxv2 += w[d];
        if ((unsigned)(x4 + 3 + d - 2) < W) wxv3 += w[d];
    }

    const float* cb = g_contrast + b * HW;
    const int ys = by0 + ty * 8;

    float4 h0 = hconv(cb, ys - 2, x4, w0, w1, w2, w3, w4);
    float4 h1 = hconv(cb, ys - 1, x4, w0, w1, w2, w3, w4);
    float4 h2 = hconv(cb, ys,     x4, w0, w1, w2, w3, w4);
    float4 h3 = hconv(cb, ys + 1, x4, w0, w1, w2, w3, w4);

    float* drow = dens_out + b * HW + ys * W + x4;

#pragma unroll
    for (int s = 0; s < 8; ++s) {
        const int y = ys + s;
        float4 h4 = hconv(cb, y + 2, x4, w0, w1, w2, w3, w4);

        float4 acc;
        acc.x = w0*h0.x + w1*h1.x + w2*h2.x + w3*h3.x + w4*h4.x;
        acc.y = w0*h0.y + w1*h1.y + w2*h2.y + w3*h3.y + w4*h4.y;
        acc.z = w0*h0.z + w1*h1.z + w2*h2.z + w3*h3.z + w4*h4.z;
        acc.w = w0*h0.w + w1*h1.w + w2*h2.w + w3*h3.w + w4*h4.w;

        float wyv = wsum;
        if (y < 2 || y >= H - 2) {
            wyv = 0.0f;
#pragma unroll
            for (int d = 0; d < 5; ++d)
                if ((unsigned)(y + d - 2) < H) wyv += w[d];
        }

        float4 dv;
        dv.x = 0.1f + 0.9f * sqrtf(fmaxf(inv * (acc.x - mn * (wyv * wxv0)), 0.0f));
        dv.y = 0.1f + 0.9f * sqrtf(fmaxf(inv * (acc.y - mn * (wyv * wxv1)), 0.0f));
        dv.z = 0.1f + 0.9f * sqrtf(fmaxf(inv * (acc.z - mn * (wyv * wxv2)), 0.0f));
        dv.w = 0.1f + 0.9f * sqrtf(fmaxf(inv * (acc.w - mn * (wyv * wxv3)), 0.0f));

        *(float4*)drow = dv;
        drow += W;

        if ((y & 1) == 0) {
            const int i = y >> 1;
            const int j0 = x4 >> 1;
            do_cell(dv.x, b, i, j0,     coords, weights);
            do_cell(dv.z, b, i, j0 + 1, coords, weights);
        }

        h0 = h1; h1 = h2; h2 = h3; h3 = h4;
    }
}

// ---------------------------------------------------------------------------
extern "C" void kernel_launch(void* const* d_in, const int* in_sizes, int n_in,
                              void* d_out, int out_size) {
    const float* img = (const float*)d_in[0];
    float* out = (float*)d_out;
    float* coords  = out;
    float* weights = out + COORDS_ELEMS;
    float* dens    = out + COORDS_ELEMS + WEIGHTS_ELEMS;

    k_main1<<<NCONTRAST + NTFB, 256>>>(img, coords);
    {
        dim3 grid(W / 128, H / 64, BATCH), block(32, 8);
        k_main2<<<grid, block>>>(dens, coords, weights);
    }
}

// round 8
// speedup vs baseline: 1.1029x; 1.1029x over previous
#include <cuda_runtime.h>
#include <cstdint>

// Problem constants (fixed by setup_inputs)
#define BATCH 8
#define H 1024
#define W 1024
#define HW (H*W)
#define TH 512
#define TW 512
#define NCELL (TH*TW)                    // 262144 = 2^18
#define COORDS_ELEMS (BATCH*NCELL*4*2)   // 16777216
#define WEIGHTS_ELEMS (BATCH*NCELL*4)    // 8388608
#define CTILES 1024                      // 32x32 contrast tiles per image
#define NCONTRAST (BATCH*CTILES)         // 8192

// Scratch (static device globals — allocation-free per harness rules)
__device__ float g_contrast[BATCH*HW];
__device__ float g_bmn[NCONTRAST];
__device__ float g_bmx[NCONTRAST];

// ---------------------------------------------------------------------------
// JAX threefry2x32, key = jax.random.key(42) -> (0, 42)
// ---------------------------------------------------------------------------
__device__ __forceinline__ unsigned rotl32(unsigned x, int r) {
    return __funnelshift_l(x, x, r);
}

__device__ __forceinline__ void threefry2x32(unsigned x0, unsigned x1,
                                             unsigned& o0, unsigned& o1) {
    const unsigned ks0 = 0u, ks1 = 42u, ks2 = 0x1BD11BF0u;
    x0 += ks0; x1 += ks1;
#define TFR(r) { x0 += x1; x1 = rotl32(x1, r); x1 ^= x0; }
    TFR(13) TFR(15) TFR(26) TFR(6)
    x0 += ks1; x1 += ks2 + 1u;
    TFR(17) TFR(29) TFR(16) TFR(24)
    x0 += ks2; x1 += ks0 + 2u;
    TFR(13) TFR(15) TFR(26) TFR(6)
    x0 += ks0; x1 += ks1 + 3u;
    TFR(17) TFR(29) TFR(16) TFR(24)
    x0 += ks1; x1 += ks2 + 4u;
    TFR(13) TFR(15) TFR(26) TFR(6)
    x0 += ks2; x1 += ks0 + 5u;
#undef TFR
    o0 = x0; o1 = x1;
}

__device__ __forceinline__ float tf_uniform(unsigned flat_idx) {
    unsigned o0, o1;
    threefry2x32(0u, flat_idx, o0, o1);
    unsigned bits = o0 ^ o1;
    return __uint_as_float((bits >> 9) | 0x3f800000u) - 1.0f;
}

// ---------------------------------------------------------------------------
// K1: fused gray + contrast + per-block min/max (proven smem version).
// Tile 32x32 per block (block 32x8, 4 rows/thread), smem 36x36 gray halo.
// ---------------------------------------------------------------------------
__global__ void k_contrast(const float* __restrict__ img) {
    __shared__ float sg[36][37];
    __shared__ float wmn[8], wmx[8];

    const int b   = blockIdx.z;
    const int bx0 = blockIdx.x * 32;
    const int by0 = blockIdx.y * 32;
    const int tx = threadIdx.x, ty = threadIdx.y;
    const int lin = ty * 32 + tx;
    const int cid = b * CTILES + blockIdx.y * 32 + blockIdx.x;

    const float* ib = img + (size_t)b * 3 * HW;

    for (int e = lin; e < 36 * 36; e += 256) {
        int r = e / 36, c = e - r * 36;
        int gy = by0 + r - 2, gx = bx0 + c - 2;
        float v = 0.0f;
        if ((unsigned)gy < H && (unsigned)gx < W) {
            int p = gy * W + gx;
            v = __ldg(ib + p) * 0.299f + __ldg(ib + HW + p) * 0.587f
              + __ldg(ib + 2 * HW + p) * 0.114f;
        }
        sg[r][c] = v;
    }
    __syncthreads();

    const int x = bx0 + tx;
    const int lx = tx + 2;
    int xl = (x == 0) ? 0 : ((x == W-1) ? W-3 : x-1);
    int xr = (x == 0) ? 2 : ((x == W-1) ? W-1 : x+1);
    const int lxl = xl - bx0 + 2, lxr = xr - bx0 + 2;

    float cmin = 3.402823466e+38f, cmax = 0.0f;

#pragma unroll
    for (int k = 0; k < 4; ++k) {
        const int ry = ty + 8 * k;
        const int y = by0 + ry;
        const int ly = ry + 2;

        float a00 = sg[ly-1][lx-1], a01 = sg[ly-1][lx], a02 = sg[ly-1][lx+1];
        float a10 = sg[ly  ][lx-1], a11 = sg[ly  ][lx], a12 = sg[ly  ][lx+1];
        float a20 = sg[ly+1][lx-1], a21 = sg[ly+1][lx], a22 = sg[ly+1][lx+1];

        float gx2 = (a02 - a00) + 2.0f * (a12 - a10) + (a22 - a20);
        float gy2 = (a20 - a00) + 2.0f * (a21 - a01) + (a22 - a02);
        float sobel = sqrtf(gx2 * gx2 + gy2 * gy2 + 1e-8f);
        float lapl  = fabsf(4.0f * a11 - a01 - a10 - a12 - a21);

        int yl = (y == 0) ? 0 : ((y == H-1) ? H-3 : y-1);
        int yr = (y == 0) ? 2 : ((y == H-1) ? H-1 : y+1);
        float dx = sg[ly][lxr] - sg[ly][lxl];
        float dy = sg[yr - by0 + 2][lx] - sg[yl - by0 + 2][lx];
        float gradm = sqrtf(dx * dx + dy * dy + 1e-8f);

        float c = 0.5f * sobel + 0.3f * lapl + 0.2f * gradm;
        g_contrast[b * HW + y * W + x] = c;
        cmin = fminf(cmin, c);
        cmax = fmaxf(cmax, c);
    }

#pragma unroll
    for (int s = 16; s > 0; s >>= 1) {
        cmin = fminf(cmin, __shfl_xor_sync(0xFFFFFFFFu, cmin, s));
        cmax = fmaxf(cmax, __shfl_xor_sync(0xFFFFFFFFu, cmax, s));
    }
    if (tx == 0) { wmn[ty] = cmin; wmx[ty] = cmax; }
    __syncthreads();
    if (lin == 0) {
        float mn = wmn[0], mx = wmx[0];
#pragma unroll
        for (int s = 1; s < 8; ++s) {
            mn = fminf(mn, wmn[s]);
            mx = fmaxf(mx, wmx[s]);
        }
        g_bmn[cid] = mn;
        g_bmx[cid] = mx;
    }
}

// ---------------------------------------------------------------------------
// horizontal 5-tap of zero-padded contrast at row y, cols x4..x4+3.
// ---------------------------------------------------------------------------
__device__ __forceinline__ float4 hconv(const float* __restrict__ cb,
                                        int y, int x4,
                                        float w0, float w1, float w2,
                                        float w3, float w4) {
    float4 r;
    if ((unsigned)y >= H) { r.x = r.y = r.z = r.w = 0.0f; return r; }
    const float* rp = cb + y * W + x4;
    float f0,f1,f2,f3,f4,f5,f6,f7;
    if (x4 >= 4) {
        float4 a = *(const float4*)(rp - 4);
        f0 = a.z; f1 = a.w;
    } else { f0 = f1 = 0.0f; }
    {
        float4 a = *(const float4*)rp;
        f2 = a.x; f3 = a.y; f4 = a.z; f5 = a.w;
    }
    if (x4 + 4 < W) {
        float4 a = *(const float4*)(rp + 4);
        f6 = a.x; f7 = a.y;
    } else { f6 = f7 = 0.0f; }
    r.x = w0*f0 + w1*f1 + w2*f2 + w3*f3 + w4*f4;
    r.y = w0*f1 + w1*f2 + w2*f3 + w3*f4 + w4*f5;
    r.z = w0*f2 + w1*f3 + w2*f4 + w3*f5 + w4*f6;
    r.w = w0*f3 + w1*f4 + w2*f5 + w3*f6 + w4*f7;
    return r;
}

// full per-cell: weights + coords (threefry when ns>1). Bit-identical to the
// reference path (same flat counter, same fp expressions).
__device__ __forceinline__ void do_cell_full(float d, int b, int i, int j,
                                             float* __restrict__ coords,
                                             float* __restrict__ weights) {
    int ns = (d > 0.7f) ? 4 : ((d > 0.4f) ? 2 : 1);
    float wv = d / (float)ns;
    int t = b * NCELL + i * TW + j;

    float4 w4;
    w4.x = wv;
    w4.y = (ns > 1) ? wv : 0.0f;
    w4.z = (ns > 3) ? wv : 0.0f;
    w4.w = (ns > 3) ? wv : 0.0f;
    ((float4*)weights)[t] = w4;

    float by = -1.0f + (float)i * (2.0f / 511.0f);
    float bx = -1.0f + (float)j * (2.0f / 511.0f);
    const float CELLSZ = 0.00390625f;   // 2/512 exact

    float4 c0, c1;
    if (ns > 1) {
        unsigned ctr = (unsigned)t * 8u;
        float u[8];
#pragma unroll
        for (int s = 0; s < 8; ++s) u[s] = tf_uniform(ctr + s);
        c0.x = by + ((u[0] - 0.5f) * 0.8f) * CELLSZ;
        c0.y = bx + ((u[1] - 0.5f) * 0.8f) * CELLSZ;
        c0.z = by + ((u[2] - 0.5f) * 0.8f) * CELLSZ;
        c0.w = bx + ((u[3] - 0.5f) * 0.8f) * CELLSZ;
        c1.x = by + ((u[4] - 0.5f) * 0.8f) * CELLSZ;
        c1.y = bx + ((u[5] - 0.5f) * 0.8f) * CELLSZ;
        c1.z = by + ((u[6] - 0.5f) * 0.8f) * CELLSZ;
        c1.w = bx + ((u[7] - 0.5f) * 0.8f) * CELLSZ;
    } else {
        c0.x = by; c0.y = bx; c0.z = by; c0.w = bx;
        c1 = c0;
    }
    float4* cp = (float4*)coords;
    cp[(size_t)t * 2]     = c0;
    cp[(size_t)t * 2 + 1] = c1;
}

// ---------------------------------------------------------------------------
// K2: register-rolling separable gaussian + density + FULL cell generation
// (weights + threefry coords). Block (32,8) -> 128x64 tile (1024 blocks);
// thread owns 4 cols x 8 rows => 8 cells. Threefry alu fills the idle issue
// slots of this latency-bound kernel.
// ---------------------------------------------------------------------------
__global__ void k_main2(float* __restrict__ dens_out,
                        float* __restrict__ coords,
                        float* __restrict__ weights) {
    __shared__ float rmn[8], rmx[8];

    const int b   = blockIdx.z;
    const int bx0 = blockIdx.x * 128;
    const int by0 = blockIdx.y * 64;
    const int tx = threadIdx.x, ty = threadIdx.y;
    const int lin = ty * 32 + tx;

    // --- batch min/max from per-block results (exact: min/max associative)
    {
        float mn_ = 3.402823466e+38f, mx_ = 0.0f;
        for (int e = lin; e < CTILES; e += 256) {
            mn_ = fminf(mn_, g_bmn[b * CTILES + e]);
            mx_ = fmaxf(mx_, g_bmx[b * CTILES + e]);
        }
#pragma unroll
        for (int s = 16; s > 0; s >>= 1) {
            mn_ = fminf(mn_, __shfl_xor_sync(0xFFFFFFFFu, mn_, s));
            mx_ = fmaxf(mx_, __shfl_xor_sync(0xFFFFFFFFu, mx_, s));
        }
        if (tx == 0) { rmn[ty] = mn_; rmx[ty] = mx_; }
    }
    __syncthreads();
    float mn = rmn[0], mx = rmx[0];
#pragma unroll
    for (int s = 1; s < 8; ++s) {
        mn = fminf(mn, rmn[s]);
        mx = fmaxf(mx, rmx[s]);
    }
    const bool ok = mx > mn;
    const float inv = ok ? 1.0f / (mx - mn) : 0.0f;

    // gaussian weights (same fp path as reference)
    const float sg2 = (5.0f / 6.0f) * (5.0f / 6.0f);
    const float e1 = expf(-0.5f / sg2);
    const float e2 = expf(-2.0f / sg2);
    const float ksum = 1.0f + 2.0f * e1 + 2.0f * e2;
    float w[5];
    w[0] = e2 / ksum; w[1] = e1 / ksum; w[2] = 1.0f / ksum; w[3] = w[1]; w[4] = w[0];
    const float w0 = w[0], w1 = w[1], w2 = w[2], w3 = w[3], w4 = w[4];
    const float wsum = ((((w[0] + w[1]) + w[2]) + w[3]) + w[4]);

    const int x4 = bx0 + tx * 4;

    float wxv0 = 0.f, wxv1 = 0.f, wxv2 = 0.f, wxv3 = 0.f;
#pragma unroll
    for (int d = 0; d < 5; ++d) {
        if ((unsigned)(x4 + 0 + d - 2) < W) wxv0 += w[d];
        if ((unsigned)(x4 + 1 + d - 2) < W) wxv1 += w[d];
        if ((unsigned)(x4 + 2 + d - 2) < W) wxv2 += w[d];
        if ((unsigned)(x4 + 3 + d - 2) < W) wxv3 += w[d];
    }

    const float* cb = g_contrast + b * HW;
    const int ys = by0 + ty * 8;

    float4 h0 = hconv(cb, ys - 2, x4, w0, w1, w2, w3, w4);
    float4 h1 = hconv(cb, ys - 1, x4, w0, w1, w2, w3, w4);
    float4 h2 = hconv(cb, ys,     x4, w0, w1, w2, w3, w4);
    float4 h3 = hconv(cb, ys + 1, x4, w0, w1, w2, w3, w4);

    float* drow = dens_out + b * HW + ys * W + x4;

#pragma unroll
    for (int s = 0; s < 8; ++s) {
        const int y = ys + s;
        float4 h4 = hconv(cb, y + 2, x4, w0, w1, w2, w3, w4);

        float4 acc;
        acc.x = w0*h0.x + w1*h1.x + w2*h2.x + w3*h3.x + w4*h4.x;
        acc.y = w0*h0.y + w1*h1.y + w2*h2.y + w3*h3.y + w4*h4.y;
        acc.z = w0*h0.z + w1*h1.z + w2*h2.z + w3*h3.z + w4*h4.z;
        acc.w = w0*h0.w + w1*h1.w + w2*h2.w + w3*h3.w + w4*h4.w;

        float wyv = wsum;
        if (y < 2 || y >= H - 2) {
            wyv = 0.0f;
#pragma unroll
            for (int d = 0; d < 5; ++d)
                if ((unsigned)(y + d - 2) < H) wyv += w[d];
        }

        float4 dv;
        dv.x = 0.1f + 0.9f * sqrtf(fmaxf(inv * (acc.x - mn * (wyv * wxv0)), 0.0f));
        dv.y = 0.1f + 0.9f * sqrtf(fmaxf(inv * (acc.y - mn * (wyv * wxv1)), 0.0f));
        dv.z = 0.1f + 0.9f * sqrtf(fmaxf(inv * (acc.z - mn * (wyv * wxv2)), 0.0f));
        dv.w = 0.1f + 0.9f * sqrtf(fmaxf(inv * (acc.w - mn * (wyv * wxv3)), 0.0f));

        *(float4*)drow = dv;
        drow += W;

        if ((y & 1) == 0) {
            const int i = y >> 1;
            const int j0 = x4 >> 1;
            do_cell_full(dv.x, b, i, j0,     coords, weights);
            do_cell_full(dv.z, b, i, j0 + 1, coords, weights);
        }

        h0 = h1; h1 = h2; h2 = h3; h3 = h4;
    }
}

// ---------------------------------------------------------------------------
extern "C" void kernel_launch(void* const* d_in, const int* in_sizes, int n_in,
                              void* d_out, int out_size) {
    const float* img = (const float*)d_in[0];
    float* out = (float*)d_out;
    float* coords  = out;
    float* weights = out + COORDS_ELEMS;
    float* dens    = out + COORDS_ELEMS + WEIGHTS_ELEMS;

    {
        dim3 grid(W / 32, H / 32, BATCH), block(32, 8);
        k_contrast<<<grid, block>>>(img);
    }
    {
        dim3 grid(W / 128, H / 64, BATCH), block(32, 8);
        k_main2<<<grid, block>>>(dens, coords, weights);
    }
}

// round 9
// speedup vs baseline: 1.1091x; 1.0055x over previous
#include <cuda_runtime.h>
#include <cstdint>

// Problem constants (fixed by setup_inputs)
#define BATCH 8
#define H 1024
#define W 1024
#define HW (H*W)
#define TH 512
#define TW 512
#define NCELL (TH*TW)                    // 262144 = 2^18
#define COORDS_ELEMS (BATCH*NCELL*4*2)   // 16777216
#define WEIGHTS_ELEMS (BATCH*NCELL*4)    // 8388608
#define CTILES 1024                      // 32x32 contrast tiles per image
#define NCONTRAST (BATCH*CTILES)         // 8192
#define NTFB 1024                        // threefry blocks (2048 cells each)
#define K1_BLOCKS (NCONTRAST + NTFB)     // 9216 = 9 * 1024

// Scratch (static device globals — allocation-free per harness rules)
__device__ float g_contrast[BATCH*HW];
__device__ float g_bmn[NCONTRAST];
__device__ float g_bmx[NCONTRAST];

// ---------------------------------------------------------------------------
// JAX threefry2x32, key = jax.random.key(42) -> (0, 42)
// ---------------------------------------------------------------------------
__device__ __forceinline__ unsigned rotl32(unsigned x, int r) {
    return __funnelshift_l(x, x, r);
}

__device__ __forceinline__ void threefry2x32(unsigned x0, unsigned x1,
                                             unsigned& o0, unsigned& o1) {
    const unsigned ks0 = 0u, ks1 = 42u, ks2 = 0x1BD11BF0u;
    x0 += ks0; x1 += ks1;
#define TFR(r) { x0 += x1; x1 = rotl32(x1, r); x1 ^= x0; }
    TFR(13) TFR(15) TFR(26) TFR(6)
    x0 += ks1; x1 += ks2 + 1u;
    TFR(17) TFR(29) TFR(16) TFR(24)
    x0 += ks2; x1 += ks0 + 2u;
    TFR(13) TFR(15) TFR(26) TFR(6)
    x0 += ks0; x1 += ks1 + 3u;
    TFR(17) TFR(29) TFR(16) TFR(24)
    x0 += ks1; x1 += ks2 + 4u;
    TFR(13) TFR(15) TFR(26) TFR(6)
    x0 += ks2; x1 += ks0 + 5u;
#undef TFR
    o0 = x0; o1 = x1;
}

__device__ __forceinline__ float tf_uniform(unsigned flat_idx) {
    unsigned o0, o1;
    threefry2x32(0u, flat_idx, o0, o1);
    unsigned bits = o0 ^ o1;
    return __uint_as_float((bits >> 9) | 0x3f800000u) - 1.0f;
}

// ---------------------------------------------------------------------------
// K1: mixed-block fat kernel. bid % 9 == 8 -> threefry coords block
// (8 cells/thread, unconditional base+offset writes); otherwise a
// gray+contrast smem tile (32x32) with per-block min/max.
// Separate co-resident block types pack the alu-saturated threefry stream
// against contrast's memory stalls (R6-proven: ~97% issue packing).
// ---------------------------------------------------------------------------
__global__ void k_main1(const float* __restrict__ img,
                        float* __restrict__ coords) {
    const int bid = blockIdx.x;
    const int lin = threadIdx.x;
    const int grp = bid / 9;

    if (bid - grp * 9 == 8) {
        // ---------------- threefry coords (img-independent) ----------------
        const int base = grp * 2048;
        const float CELLSZ = 0.00390625f;          // 2/512 exact
#pragma unroll
        for (int k = 0; k < 8; ++k) {
            const int t = base + k * 256 + lin;
            const int cell = t & (NCELL - 1);
            const int i = cell >> 9;
            const int j = cell & (TW - 1);

            float by = -1.0f + (float)i * (2.0f / 511.0f);
            float bx = -1.0f + (float)j * (2.0f / 511.0f);

            unsigned ctr = (unsigned)t * 8u;
            float u[8];
#pragma unroll
            for (int s = 0; s < 8; ++s) u[s] = tf_uniform(ctr + s);

            float4 c0, c1;
            c0.x = by + ((u[0] - 0.5f) * 0.8f) * CELLSZ;
            c0.y = bx + ((u[1] - 0.5f) * 0.8f) * CELLSZ;
            c0.z = by + ((u[2] - 0.5f) * 0.8f) * CELLSZ;
            c0.w = bx + ((u[3] - 0.5f) * 0.8f) * CELLSZ;
            c1.x = by + ((u[4] - 0.5f) * 0.8f) * CELLSZ;
            c1.y = bx + ((u[5] - 0.5f) * 0.8f) * CELLSZ;
            c1.z = by + ((u[6] - 0.5f) * 0.8f) * CELLSZ;
            c1.w = bx + ((u[7] - 0.5f) * 0.8f) * CELLSZ;

            float4* cp = (float4*)coords;
            cp[(size_t)t * 2]     = c0;
            cp[(size_t)t * 2 + 1] = c1;
        }
    } else {
        // ---------------- contrast tile (32x32, smem gray halo) ------------
        __shared__ float sg[36][37];
        __shared__ float wmn[8], wmx[8];

        const int cid  = bid - grp;                // 0..8191
        const int b    = cid >> 10;
        const int tile = cid & (CTILES - 1);
        const int by0 = (tile >> 5) * 32;
        const int bx0 = (tile & 31) * 32;
        const int tx = lin & 31, ty = lin >> 5;

        const float* ib = img + (size_t)b * 3 * HW;

        for (int e = lin; e < 36 * 36; e += 256) {
            int r = e / 36, c = e - r * 36;
            int gy = by0 + r - 2, gx = bx0 + c - 2;
            float v = 0.0f;
            if ((unsigned)gy < H && (unsigned)gx < W) {
                int p = gy * W + gx;
                v = __ldg(ib + p) * 0.299f + __ldg(ib + HW + p) * 0.587f
                  + __ldg(ib + 2 * HW + p) * 0.114f;
            }
            sg[r][c] = v;
        }
        __syncthreads();

        const int x = bx0 + tx;
        const int lx = tx + 2;
        int xl = (x == 0) ? 0 : ((x == W-1) ? W-3 : x-1);
        int xr = (x == 0) ? 2 : ((x == W-1) ? W-1 : x+1);
        const int lxl = xl - bx0 + 2, lxr = xr - bx0 + 2;

        float cmin = 3.402823466e+38f, cmax = 0.0f;

#pragma unroll
        for (int k = 0; k < 4; ++k) {
            const int ry = ty + 8 * k;
            const int y = by0 + ry;
            const int ly = ry + 2;

            float a00 = sg[ly-1][lx-1], a01 = sg[ly-1][lx], a02 = sg[ly-1][lx+1];
            float a10 = sg[ly  ][lx-1], a11 = sg[ly  ][lx], a12 = sg[ly  ][lx+1];
            float a20 = sg[ly+1][lx-1], a21 = sg[ly+1][lx], a22 = sg[ly+1][lx+1];

            float gx2 = (a02 - a00) + 2.0f * (a12 - a10) + (a22 - a20);
            float gy2 = (a20 - a00) + 2.0f * (a21 - a01) + (a22 - a02);
            float sobel = sqrtf(gx2 * gx2 + gy2 * gy2 + 1e-8f);
            float lapl  = fabsf(4.0f * a11 - a01 - a10 - a12 - a21);

            int yl = (y == 0) ? 0 : ((y == H-1) ? H-3 : y-1);
            int yr = (y == 0) ? 2 : ((y == H-1) ? H-1 : y+1);
            float dx = sg[ly][lxr] - sg[ly][lxl];
            float dy = sg[yr - by0 + 2][lx] - sg[yl - by0 + 2][lx];
            float gradm = sqrtf(dx * dx + dy * dy + 1e-8f);

            float c = 0.5f * sobel + 0.3f * lapl + 0.2f * gradm;
            g_contrast[b * HW + y * W + x] = c;
            cmin = fminf(cmin, c);
            cmax = fmaxf(cmax, c);
        }

#pragma unroll
        for (int s = 16; s > 0; s >>= 1) {
            cmin = fminf(cmin, __shfl_xor_sync(0xFFFFFFFFu, cmin, s));
            cmax = fmaxf(cmax, __shfl_xor_sync(0xFFFFFFFFu, cmax, s));
        }
        if (tx == 0) { wmn[ty] = cmin; wmx[ty] = cmax; }
        __syncthreads();
        if (lin == 0) {
            float mn = wmn[0], mx = wmx[0];
#pragma unroll
            for (int s = 1; s < 8; ++s) {
                mn = fminf(mn, wmn[s]);
                mx = fmaxf(mx, wmx[s]);
            }
            g_bmn[cid] = mn;
            g_bmx[cid] = mx;
        }
    }
}

// ---------------------------------------------------------------------------
// horizontal 5-tap of zero-padded contrast at row y, cols x4..x4+3.
// ---------------------------------------------------------------------------
__device__ __forceinline__ float4 hconv(const float* __restrict__ cb,
                                        int y, int x4,
                                        float w0, float w1, float w2,
                                        float w3, float w4) {
    float4 r;
    if ((unsigned)y >= H) { r.x = r.y = r.z = r.w = 0.0f; return r; }
    const float* rp = cb + y * W + x4;
    float f0,f1,f2,f3,f4,f5,f6,f7;
    if (x4 >= 4) {
        float4 a = *(const float4*)(rp - 4);
        f0 = a.z; f1 = a.w;
    } else { f0 = f1 = 0.0f; }
    {
        float4 a = *(const float4*)rp;
        f2 = a.x; f3 = a.y; f4 = a.z; f5 = a.w;
    }
    if (x4 + 4 < W) {
        float4 a = *(const float4*)(rp + 4);
        f6 = a.x; f7 = a.y;
    } else { f6 = f7 = 0.0f; }
    r.x = w0*f0 + w1*f1 + w2*f2 + w3*f3 + w4*f4;
    r.y = w0*f1 + w1*f2 + w2*f3 + w3*f4 + w4*f5;
    r.z = w0*f2 + w1*f3 + w2*f4 + w3*f5 + w4*f6;
    r.w = w0*f3 + w1*f4 + w2*f5 + w3*f6 + w4*f7;
    return r;
}

// per-cell weights + ns==1 coords fixup (K1 wrote base+offset coords;
// launch boundary orders the writes).
__device__ __forceinline__ void do_cell(float d, int b, int i, int j,
                                        float* __restrict__ coords,
                                        float* __restrict__ weights) {
    int ns = (d > 0.7f) ? 4 : ((d > 0.4f) ? 2 : 1);
    float wv = d / (float)ns;
    int t = b * NCELL + i * TW + j;
    float4 w4;
    w4.x = wv;
    w4.y = (ns > 1) ? wv : 0.0f;
    w4.z = (ns > 3) ? wv : 0.0f;
    w4.w = (ns > 3) ? wv : 0.0f;
    ((float4*)weights)[t] = w4;
    if (ns == 1) {
        float by = -1.0f + (float)i * (2.0f / 511.0f);
        float bx = -1.0f + (float)j * (2.0f / 511.0f);
        float4 c0; c0.x = by; c0.y = bx; c0.z = by; c0.w = bx;
        float4* cp = (float4*)coords;
        cp[(size_t)t * 2]     = c0;
        cp[(size_t)t * 2 + 1] = c0;
    }
}

// ---------------------------------------------------------------------------
// K2: register-rolling separable gaussian + density + weights + fixup.
// Block (32,8) -> 128x64 tile (1024 blocks); thread owns 4 cols x 8 rows.
// launch_bounds forces <=64 regs -> 4 CTAs/SM to lift the latency floor.
// ---------------------------------------------------------------------------
__global__ void __launch_bounds__(256, 4)
k_main2(float* __restrict__ dens_out,
        float* __restrict__ coords,
        float* __restrict__ weights) {
    __shared__ float rmn[8], rmx[8];

    const int b   = blockIdx.z;
    const int bx0 = blockIdx.x * 128;
    const int by0 = blockIdx.y * 64;
    const int tx = threadIdx.x, ty = threadIdx.y;
    const int lin = ty * 32 + tx;

    // --- batch min/max from per-block results (exact: min/max associative)
    {
        float mn_ = 3.402823466e+38f, mx_ = 0.0f;
        for (int e = lin; e < CTILES; e += 256) {
            mn_ = fminf(mn_, g_bmn[b * CTILES + e]);
            mx_ = fmaxf(mx_, g_bmx[b * CTILES + e]);
        }
#pragma unroll
        for (int s = 16; s > 0; s >>= 1) {
            mn_ = fminf(mn_, __shfl_xor_sync(0xFFFFFFFFu, mn_, s));
            mx_ = fmaxf(mx_, __shfl_xor_sync(0xFFFFFFFFu, mx_, s));
        }
        if (tx == 0) { rmn[ty] = mn_; rmx[ty] = mx_; }
    }
    __syncthreads();
    float mn = rmn[0], mx = rmx[0];
#pragma unroll
    for (int s = 1; s < 8; ++s) {
        mn = fminf(mn, rmn[s]);
        mx = fmaxf(mx, rmx[s]);
    }
    const bool ok = mx > mn;
    const float inv = ok ? 1.0f / (mx - mn) : 0.0f;

    // gaussian weights (same fp path as reference)
    const float sg2 = (5.0f / 6.0f) * (5.0f / 6.0f);
    const float e1 = expf(-0.5f / sg2);
    const float e2 = expf(-2.0f / sg2);
    const float ksum = 1.0f + 2.0f * e1 + 2.0f * e2;
    float w[5];
    w[0] = e2 / ksum; w[1] = e1 / ksum; w[2] = 1.0f / ksum; w[3] = w[1]; w[4] = w[0];
    const float w0 = w[0], w1 = w[1], w2 = w[2], w3 = w[3], w4 = w[4];
    const float wsum = ((((w[0] + w[1]) + w[2]) + w[3]) + w[4]);

    const int x4 = bx0 + tx * 4;

    float wxv0 = 0.f, wxv1 = 0.f, wxv2 = 0.f, wxv3 = 0.f;
#pragma unroll
    for (int d = 0; d < 5; ++d) {
        if ((unsigned)(x4 + 0 + d - 2) < W) wxv0 += w[d];
        if ((unsigned)(x4 + 1 + d - 2) < W) wxv1 += w[d];
        if ((unsigned)(x4 + 2 + d - 2) < W) wxv2 += w[d];
        if ((unsigned)(x4 + 3 + d - 2) < W) wxv3 += w[d];
    }

    const float* cb = g_contrast + b * HW;
    const int ys = by0 + ty * 8;

    float4 h0 = hconv(cb, ys - 2, x4, w0, w1, w2, w3, w4);
    float4 h1 = hconv(cb, ys - 1, x4, w0, w1, w2, w3, w4);
    float4 h2 = hconv(cb, ys,     x4, w0, w1, w2, w3, w4);
    float4 h3 = hconv(cb, ys + 1, x4, w0, w1, w2, w3, w4);

    float* drow = dens_out + b * HW + ys * W + x4;

#pragma unroll
    for (int s = 0; s < 8; ++s) {
        const int y = ys + s;
        float4 h4 = hconv(cb, y + 2, x4, w0, w1, w2, w3, w4);

        float4 acc;
        acc.x = w0*h0.x + w1*h1.x + w2*h2.x + w3*h3.x + w4*h4.x;
        acc.y = w0*h0.y + w1*h1.y + w2*h2.y + w3*h3.y + w4*h4.y;
        acc.z = w0*h0.z + w1*h1.z + w2*h2.z + w3*h3.z + w4*h4.z;
        acc.w = w0*h0.w + w1*h1.w + w2*h2.w + w3*h3.w + w4*h4.w;

        float wyv = wsum;
        if (y < 2 || y >= H - 2) {
            wyv = 0.0f;
#pragma unroll
            for (int d = 0; d < 5; ++d)
                if ((unsigned)(y + d - 2) < H) wyv += w[d];
        }

        float4 dv;
        dv.x = 0.1f + 0.9f * sqrtf(fmaxf(inv * (acc.x - mn * (wyv * wxv0)), 0.0f));
        dv.y = 0.1f + 0.9f * sqrtf(fmaxf(inv * (acc.y - mn * (wyv * wxv1)), 0.0f));
        dv.z = 0.1f + 0.9f * sqrtf(fmaxf(inv * (acc.z - mn * (wyv * wxv2)), 0.0f));
        dv.w = 0.1f + 0.9f * sqrtf(fmaxf(inv * (acc.w - mn * (wyv * wxv3)), 0.0f));

        *(float4*)drow = dv;
        drow += W;

        if ((y & 1) == 0) {
            const int i = y >> 1;
            const int j0 = x4 >> 1;
            do_cell(dv.x, b, i, j0,     coords, weights);
            do_cell(dv.z, b, i, j0 + 1, coords, weights);
        }

        h0 = h1; h1 = h2; h2 = h3; h3 = h4;
    }
}

// ---------------------------------------------------------------------------
extern "C" void kernel_launch(void* const* d_in, const int* in_sizes, int n_in,
                              void* d_out, int out_size) {
    const float* img = (const float*)d_in[0];
    float* out = (float*)d_out;
    float* coords  = out;
    float* weights = out + COORDS_ELEMS;
    float* dens    = out + COORDS_ELEMS + WEIGHTS_ELEMS;

    k_main1<<<K1_BLOCKS, 256>>>(img, coords);
    {
        dim3 grid(W / 128, H / 64, BATCH), block(32, 8);
        k_main2<<<grid, block>>>(dens, coords, weights);
    }
}

// round 10
// speedup vs baseline: 1.2601x; 1.1362x over previous
#include <cuda_runtime.h>
#include <cstdint>

// Problem constants (fixed by setup_inputs)
#define BATCH 8
#define H 1024
#define W 1024
#define HW (H*W)
#define TH 512
#define TW 512
#define NCELL (TH*TW)                    // 262144 = 2^18
#define COORDS_ELEMS (BATCH*NCELL*4*2)   // 16777216
#define WEIGHTS_ELEMS (BATCH*NCELL*4)    // 8388608
#define CTILES 1024                      // 32x32 contrast tiles per image
#define NCONTRAST (BATCH*CTILES)         // 8192

// Scratch (static device globals — allocation-free per harness rules)
__device__ float g_contrast[BATCH*HW];
__device__ float g_bmn[NCONTRAST];
__device__ float g_bmx[NCONTRAST];

// ---------------------------------------------------------------------------
// JAX threefry2x32, key = jax.random.key(42) -> (0, 42)
// ---------------------------------------------------------------------------
__device__ __forceinline__ unsigned rotl32(unsigned x, int r) {
    return __funnelshift_l(x, x, r);
}

__device__ __forceinline__ void threefry2x32(unsigned x0, unsigned x1,
                                             unsigned& o0, unsigned& o1) {
    const unsigned ks0 = 0u, ks1 = 42u, ks2 = 0x1BD11BF0u;
    x0 += ks0; x1 += ks1;
#define TFR(r) { x0 += x1; x1 = rotl32(x1, r); x1 ^= x0; }
    TFR(13) TFR(15) TFR(26) TFR(6)
    x0 += ks1; x1 += ks2 + 1u;
    TFR(17) TFR(29) TFR(16) TFR(24)
    x0 += ks2; x1 += ks0 + 2u;
    TFR(13) TFR(15) TFR(26) TFR(6)
    x0 += ks0; x1 += ks1 + 3u;
    TFR(17) TFR(29) TFR(16) TFR(24)
    x0 += ks1; x1 += ks2 + 4u;
    TFR(13) TFR(15) TFR(26) TFR(6)
    x0 += ks2; x1 += ks0 + 5u;
#undef TFR
    o0 = x0; o1 = x1;
}

__device__ __forceinline__ float tf_uniform(unsigned flat_idx) {
    unsigned o0, o1;
    threefry2x32(0u, flat_idx, o0, o1);
    unsigned bits = o0 ^ o1;
    return __uint_as_float((bits >> 9) | 0x3f800000u) - 1.0f;
}

// ---------------------------------------------------------------------------
// K1: strict-alternation mixed-block kernel (R6-proven packing, ~97% issue).
// Even bid -> contrast tile (mem/issue-mixed), odd bid -> threefry coords
// block, 1 cell per thread (duration-matched with contrast blocks).
// ---------------------------------------------------------------------------
__global__ void k_main1(const float* __restrict__ img,
                        float* __restrict__ coords) {
    __shared__ float sg[36][37];
    __shared__ float wmn[8], wmx[8];

    const int bid = blockIdx.x;
    const int lin = threadIdx.x;

    if ((bid & 1) == 0) {
        // ---------------- contrast tile (32x32, smem gray halo) ------------
        const int cid  = bid >> 1;                 // 0..8191
        const int b    = cid >> 10;
        const int tile = cid & (CTILES - 1);
        const int by0 = (tile >> 5) * 32;
        const int bx0 = (tile & 31) * 32;
        const int tx = lin & 31, ty = lin >> 5;

        const float* ib = img + (size_t)b * 3 * HW;

        for (int e = lin; e < 36 * 36; e += 256) {
            int r = e / 36, c = e - r * 36;
            int gy = by0 + r - 2, gx = bx0 + c - 2;
            float v = 0.0f;
            if ((unsigned)gy < H && (unsigned)gx < W) {
                int p = gy * W + gx;
                v = __ldg(ib + p) * 0.299f + __ldg(ib + HW + p) * 0.587f
                  + __ldg(ib + 2 * HW + p) * 0.114f;
            }
            sg[r][c] = v;
        }
        __syncthreads();

        const int x = bx0 + tx;
        const int lx = tx + 2;
        int xl = (x == 0) ? 0 : ((x == W-1) ? W-3 : x-1);
        int xr = (x == 0) ? 2 : ((x == W-1) ? W-1 : x+1);
        const int lxl = xl - bx0 + 2, lxr = xr - bx0 + 2;

        float cmin = 3.402823466e+38f, cmax = 0.0f;

#pragma unroll
        for (int k = 0; k < 4; ++k) {
            const int ry = ty + 8 * k;
            const int y = by0 + ry;
            const int ly = ry + 2;

            float a00 = sg[ly-1][lx-1], a01 = sg[ly-1][lx], a02 = sg[ly-1][lx+1];
            float a10 = sg[ly  ][lx-1], a11 = sg[ly  ][lx], a12 = sg[ly  ][lx+1];
            float a20 = sg[ly+1][lx-1], a21 = sg[ly+1][lx], a22 = sg[ly+1][lx+1];

            float gx2 = (a02 - a00) + 2.0f * (a12 - a10) + (a22 - a20);
            float gy2 = (a20 - a00) + 2.0f * (a21 - a01) + (a22 - a02);
            float sobel = sqrtf(gx2 * gx2 + gy2 * gy2 + 1e-8f);
            float lapl  = fabsf(4.0f * a11 - a01 - a10 - a12 - a21);

            int yl = (y == 0) ? 0 : ((y == H-1) ? H-3 : y-1);
            int yr = (y == 0) ? 2 : ((y == H-1) ? H-1 : y+1);
            float dx = sg[ly][lxr] - sg[ly][lxl];
            float dy = sg[yr - by0 + 2][lx] - sg[yl - by0 + 2][lx];
            float gradm = sqrtf(dx * dx + dy * dy + 1e-8f);

            float c = 0.5f * sobel + 0.3f * lapl + 0.2f * gradm;
            g_contrast[b * HW + y * W + x] = c;
            cmin = fminf(cmin, c);
            cmax = fmaxf(cmax, c);
        }

#pragma unroll
        for (int s = 16; s > 0; s >>= 1) {
            cmin = fminf(cmin, __shfl_xor_sync(0xFFFFFFFFu, cmin, s));
            cmax = fmaxf(cmax, __shfl_xor_sync(0xFFFFFFFFu, cmax, s));
        }
        if (tx == 0) { wmn[ty] = cmin; wmx[ty] = cmax; }
        __syncthreads();
        if (lin == 0) {
            float mn = wmn[0], mx = wmx[0];
#pragma unroll
            for (int s = 1; s < 8; ++s) {
                mn = fminf(mn, wmn[s]);
                mx = fmaxf(mx, wmx[s]);
            }
            g_bmn[cid] = mn;
            g_bmx[cid] = mx;
        }
    } else {
        // ---------------- threefry coords (img-independent, 1 cell/thread) -
        const int t = (bid >> 1) * 256 + lin;   // 0 .. 2M-1
        const int cell = t & (NCELL - 1);
        const int i = cell >> 9;
        const int j = cell & (TW - 1);

        float by = -1.0f + (float)i * (2.0f / 511.0f);
        float bx = -1.0f + (float)j * (2.0f / 511.0f);
        const float CELLSZ = 0.00390625f;   // 2/512 exact

        unsigned ctr = (unsigned)t * 8u;
        float u[8];
#pragma unroll
        for (int s = 0; s < 8; ++s) u[s] = tf_uniform(ctr + s);

        float4 c0, c1;
        c0.x = by + ((u[0] - 0.5f) * 0.8f) * CELLSZ;
        c0.y = bx + ((u[1] - 0.5f) * 0.8f) * CELLSZ;
        c0.z = by + ((u[2] - 0.5f) * 0.8f) * CELLSZ;
        c0.w = bx + ((u[3] - 0.5f) * 0.8f) * CELLSZ;
        c1.x = by + ((u[4] - 0.5f) * 0.8f) * CELLSZ;
        c1.y = bx + ((u[5] - 0.5f) * 0.8f) * CELLSZ;
        c1.z = by + ((u[6] - 0.5f) * 0.8f) * CELLSZ;
        c1.w = bx + ((u[7] - 0.5f) * 0.8f) * CELLSZ;

        float4* cp = (float4*)coords;
        cp[(size_t)t * 2]     = c0;
        cp[(size_t)t * 2 + 1] = c1;
    }
}

// ---------------------------------------------------------------------------
// horizontal 5-tap of zero-padded contrast at row y, cols x4..x4+3.
// ---------------------------------------------------------------------------
__device__ __forceinline__ float4 hconv(const float* __restrict__ cb,
                                        int y, int x4,
                                        float w0, float w1, float w2,
                                        float w3, float w4) {
    float4 r;
    if ((unsigned)y >= H) { r.x = r.y = r.z = r.w = 0.0f; return r; }
    const float* rp = cb + y * W + x4;
    float f0,f1,f2,f3,f4,f5,f6,f7;
    if (x4 >= 4) {
        float4 a = *(const float4*)(rp - 4);
        f0 = a.z; f1 = a.w;
    } else { f0 = f1 = 0.0f; }
    {
        float4 a = *(const float4*)rp;
        f2 = a.x; f3 = a.y; f4 = a.z; f5 = a.w;
    }
    if (x4 + 4 < W) {
        float4 a = *(const float4*)(rp + 4);
        f6 = a.x; f7 = a.y;
    } else { f6 = f7 = 0.0f; }
    r.x = w0*f0 + w1*f1 + w2*f2 + w3*f3 + w4*f4;
    r.y = w0*f1 + w1*f2 + w2*f3 + w3*f4 + w4*f5;
    r.z = w0*f2 + w1*f3 + w2*f4 + w3*f5 + w4*f6;
    r.w = w0*f3 + w1*f4 + w2*f5 + w3*f6 + w4*f7;
    return r;
}

// per-cell weights + ns==1 coords fixup (K1 wrote base+offset coords;
// launch boundary orders the writes).
__device__ __forceinline__ void do_cell(float d, int b, int i, int j,
                                        float* __restrict__ coords,
                                        float* __restrict__ weights) {
    int ns = (d > 0.7f) ? 4 : ((d > 0.4f) ? 2 : 1);
    float wv = d / (float)ns;
    int t = b * NCELL + i * TW + j;
    float4 w4;
    w4.x = wv;
    w4.y = (ns > 1) ? wv : 0.0f;
    w4.z = (ns > 3) ? wv : 0.0f;
    w4.w = (ns > 3) ? wv : 0.0f;
    ((float4*)weights)[t] = w4;
    if (ns == 1) {
        float by = -1.0f + (float)i * (2.0f / 511.0f);
        float bx = -1.0f + (float)j * (2.0f / 511.0f);
        float4 c0; c0.x = by; c0.y = bx; c0.z = by; c0.w = bx;
        float4* cp = (float4*)coords;
        cp[(size_t)t * 2]     = c0;
        cp[(size_t)t * 2 + 1] = c0;
    }
}

// ---------------------------------------------------------------------------
// K2: register-rolling separable gaussian + density + weights + fixup.
// Block (32,8) -> 128x64 tile (1024 blocks); thread owns 4 cols x 8 rows.
// launch_bounds forces <=64 regs -> 4 CTAs/SM.
// ---------------------------------------------------------------------------
__global__ void __launch_bounds__(256, 4)
k_main2(float* __restrict__ dens_out,
        float* __restrict__ coords,
        float* __restrict__ weights) {
    __shared__ float rmn[8], rmx[8];

    const int b   = blockIdx.z;
    const int bx0 = blockIdx.x * 128;
    const int by0 = blockIdx.y * 64;
    const int tx = threadIdx.x, ty = threadIdx.y;
    const int lin = ty * 32 + tx;

    // --- batch min/max from per-block results (exact: min/max associative)
    {
        float mn_ = 3.402823466e+38f, mx_ = 0.0f;
        for (int e = lin; e < CTILES; e += 256) {
            mn_ = fminf(mn_, g_bmn[b * CTILES + e]);
            mx_ = fmaxf(mx_, g_bmx[b * CTILES + e]);
        }
#pragma unroll
        for (int s = 16; s > 0; s >>= 1) {
            mn_ = fminf(mn_, __shfl_xor_sync(0xFFFFFFFFu, mn_, s));
            mx_ = fmaxf(mx_, __shfl_xor_sync(0xFFFFFFFFu, mx_, s));
        }
        if (tx == 0) { rmn[ty] = mn_; rmx[ty] = mx_; }
    }
    __syncthreads();
    float mn = rmn[0], mx = rmx[0];
#pragma unroll
    for (int s = 1; s < 8; ++s) {
        mn = fminf(mn, rmn[s]);
        mx = fmaxf(mx, rmx[s]);
    }
    const bool ok = mx > mn;
    const float inv = ok ? 1.0f / (mx - mn) : 0.0f;

    // gaussian weights (same fp path as reference)
    const float sg2 = (5.0f / 6.0f) * (5.0f / 6.0f);
    const float e1 = expf(-0.5f / sg2);
    const float e2 = expf(-2.0f / sg2);
    const float ksum = 1.0f + 2.0f * e1 + 2.0f * e2;
    float w[5];
    w[0] = e2 / ksum; w[1] = e1 / ksum; w[2] = 1.0f / ksum; w[3] = w[1]; w[4] = w[0];
    const float w0 = w[0], w1 = w[1], w2 = w[2], w3 = w[3], w4 = w[4];
    const float wsum = ((((w[0] + w[1]) + w[2]) + w[3]) + w[4]);

    const int x4 = bx0 + tx * 4;

    float wxv0 = 0.f, wxv1 = 0.f, wxv2 = 0.f, wxv3 = 0.f;
#pragma unroll
    for (int d = 0; d < 5; ++d) {
        if ((unsigned)(x4 + 0 + d - 2) < W) wxv0 += w[d];
        if ((unsigned)(x4 + 1 + d - 2) < W) wxv1 += w[d];
        if ((unsigned)(x4 + 2 + d - 2) < W) wxv2 += w[d];
        if ((unsigned)(x4 + 3 + d - 2) < W) wxv3 += w[d];
    }

    const float* cb = g_contrast + b * HW;
    const int ys = by0 + ty * 8;

    float4 h0 = hconv(cb, ys - 2, x4, w0, w1, w2, w3, w4);
    float4 h1 = hconv(cb, ys - 1, x4, w0, w1, w2, w3, w4);
    float4 h2 = hconv(cb, ys,     x4, w0, w1, w2, w3, w4);
    float4 h3 = hconv(cb, ys + 1, x4, w0, w1, w2, w3, w4);

    float* drow = dens_out + b * HW + ys * W + x4;

#pragma unroll
    for (int s = 0; s < 8; ++s) {
        const int y = ys + s;
        float4 h4 = hconv(cb, y + 2, x4, w0, w1, w2, w3, w4);

        float4 acc;
        acc.x = w0*h0.x + w1*h1.x + w2*h2.x + w3*h3.x + w4*h4.x;
        acc.y = w0*h0.y + w1*h1.y + w2*h2.y + w3*h3.y + w4*h4.y;
        acc.z = w0*h0.z + w1*h1.z + w2*h2.z + w3*h3.z + w4*h4.z;
        acc.w = w0*h0.w + w1*h1.w + w2*h2.w + w3*h3.w + w4*h4.w;

        float wyv = wsum;
        if (y < 2 || y >= H - 2) {
            wyv = 0.0f;
#pragma unroll
            for (int d = 0; d < 5; ++d)
                if ((unsigned)(y + d - 2) < H) wyv += w[d];
        }

        float4 dv;
        dv.x = 0.1f + 0.9f * sqrtf(fmaxf(inv * (acc.x - mn * (wyv * wxv0)), 0.0f));
        dv.y = 0.1f + 0.9f * sqrtf(fmaxf(inv * (acc.y - mn * (wyv * wxv1)), 0.0f));
        dv.z = 0.1f + 0.9f * sqrtf(fmaxf(inv * (acc.z - mn * (wyv * wxv2)), 0.0f));
        dv.w = 0.1f + 0.9f * sqrtf(fmaxf(inv * (acc.w - mn * (wyv * wxv3)), 0.0f));

        *(float4*)drow = dv;
        drow += W;

        if ((y & 1) == 0) {
            const int i = y >> 1;
            const int j0 = x4 >> 1;
            do_cell(dv.x, b, i, j0,     coords, weights);
            do_cell(dv.z, b, i, j0 + 1, coords, weights);
        }

        h0 = h1; h1 = h2; h2 = h3; h3 = h4;
    }
}

// ---------------------------------------------------------------------------
extern "C" void kernel_launch(void* const* d_in, const int* in_sizes, int n_in,
                              void* d_out, int out_size) {
    const float* img = (const float*)d_in[0];
    float* out = (float*)d_out;
    float* coords  = out;
    float* weights = out + COORDS_ELEMS;
    float* dens    = out + COORDS_ELEMS + WEIGHTS_ELEMS;

    k_main1<<<2 * NCONTRAST, 256>>>(img, coords);
    {
        dim3 grid(W / 128, H / 64, BATCH), block(32, 8);
        k_main2<<<grid, block>>>(dens, coords, weights);
    }
}

// round 11
// speedup vs baseline: 1.2804x; 1.0161x over previous
#include <cuda_runtime.h>
#include <cstdint>

// Problem constants (fixed by setup_inputs)
#define BATCH 8
#define H 1024
#define W 1024
#define HW (H*W)
#define TH 512
#define TW 512
#define NCELL (TH*TW)                    // 262144 = 2^18
#define COORDS_ELEMS (BATCH*NCELL*4*2)   // 16777216
#define WEIGHTS_ELEMS (BATCH*NCELL*4)    // 8388608
#define CTILES 1024                      // 32x32 contrast tiles per image
#define NCONTRAST (BATCH*CTILES)         // 8192

// Scratch (static device globals — allocation-free per harness rules)
__device__ float g_contrast[BATCH*HW];
__device__ float g_bmn[NCONTRAST];
__device__ float g_bmx[NCONTRAST];

// ---------------------------------------------------------------------------
// JAX threefry2x32, key = jax.random.key(42) -> (0, 42)
// ---------------------------------------------------------------------------
__device__ __forceinline__ unsigned rotl32(unsigned x, int r) {
    return __funnelshift_l(x, x, r);
}

__device__ __forceinline__ void threefry2x32(unsigned x0, unsigned x1,
                                             unsigned& o0, unsigned& o1) {
    const unsigned ks0 = 0u, ks1 = 42u, ks2 = 0x1BD11BF0u;
    x0 += ks0; x1 += ks1;
#define TFR(r) { x0 += x1; x1 = rotl32(x1, r); x1 ^= x0; }
    TFR(13) TFR(15) TFR(26) TFR(6)
    x0 += ks1; x1 += ks2 + 1u;
    TFR(17) TFR(29) TFR(16) TFR(24)
    x0 += ks2; x1 += ks0 + 2u;
    TFR(13) TFR(15) TFR(26) TFR(6)
    x0 += ks0; x1 += ks1 + 3u;
    TFR(17) TFR(29) TFR(16) TFR(24)
    x0 += ks1; x1 += ks2 + 4u;
    TFR(13) TFR(15) TFR(26) TFR(6)
    x0 += ks2; x1 += ks0 + 5u;
#undef TFR
    o0 = x0; o1 = x1;
}

__device__ __forceinline__ float tf_uniform(unsigned flat_idx) {
    unsigned o0, o1;
    threefry2x32(0u, flat_idx, o0, o1);
    unsigned bits = o0 ^ o1;
    return __uint_as_float((bits >> 9) | 0x3f800000u) - 1.0f;
}

// ---------------------------------------------------------------------------
// K1: strict-alternation mixed-block kernel. Even bid -> contrast tile
// (strip-restructured compute: 18 LDS / 4 outputs, float4 stores),
// odd bid -> threefry coords block (1 cell/thread, duration-matched).
// ---------------------------------------------------------------------------
__global__ void k_main1(const float* __restrict__ img,
                        float* __restrict__ coords) {
    __shared__ float sg[36][37];
    __shared__ float wmn[8], wmx[8];

    const int bid = blockIdx.x;
    const int lin = threadIdx.x;

    if ((bid & 1) == 0) {
        // ---------------- contrast tile (32x32, smem gray halo) ------------
        const int cid  = bid >> 1;                 // 0..8191
        const int b    = cid >> 10;
        const int tile = cid & (CTILES - 1);
        const int by0 = (tile >> 5) * 32;
        const int bx0 = (tile & 31) * 32;

        const float* ib = img + (size_t)b * 3 * HW;

        // gray fill: interior fast path (no predicates) vs border path
        if (bx0 != 0 && bx0 != W - 32 && by0 != 0 && by0 != H - 32) {
            for (int e = lin; e < 36 * 36; e += 256) {
                int r = e / 36, c = e - r * 36;
                int p = (by0 + r - 2) * W + (bx0 + c - 2);
                sg[r][c] = __ldg(ib + p) * 0.299f + __ldg(ib + HW + p) * 0.587f
                         + __ldg(ib + 2 * HW + p) * 0.114f;
            }
        } else {
            for (int e = lin; e < 36 * 36; e += 256) {
                int r = e / 36, c = e - r * 36;
                int gy = by0 + r - 2, gx = bx0 + c - 2;
                float v = 0.0f;
                if ((unsigned)gy < H && (unsigned)gx < W) {
                    int p = gy * W + gx;
                    v = __ldg(ib + p) * 0.299f + __ldg(ib + HW + p) * 0.587f
                      + __ldg(ib + 2 * HW + p) * 0.114f;
                }
                sg[r][c] = v;
            }
        }
        __syncthreads();

        // compute: 8 strips (4 cols) x 32 rows; one strip-row per thread
        const int strip = lin & 7;                 // 0..7
        const int ry    = lin >> 3;                // 0..31
        const int y     = by0 + ry;
        const int ly    = ry + 2;
        const int c0    = strip * 4;               // tile-local first col
        const int lc    = c0 + 2;                  // sg col of first output

        // 3-row x 6-col register window
        float r0[6], rc[6], r1[6];
#pragma unroll
        for (int i = 0; i < 6; ++i) {
            r0[i] = sg[ly - 1][lc - 1 + i];
            rc[i] = sg[ly    ][lc - 1 + i];
            r1[i] = sg[ly + 1][lc - 1 + i];
        }

        float cmin = 3.402823466e+38f, cmax = 0.0f;
        float cc[4];
#pragma unroll
        for (int i = 0; i < 4; ++i) {
            float a00 = r0[i], a01 = r0[i+1], a02 = r0[i+2];
            float a10 = rc[i], a11 = rc[i+1], a12 = rc[i+2];
            float a20 = r1[i], a21 = r1[i+1], a22 = r1[i+2];

            float gx2 = (a02 - a00) + 2.0f * (a12 - a10) + (a22 - a20);
            float gy2 = (a20 - a00) + 2.0f * (a21 - a01) + (a22 - a02);
            float sobel = sqrtf(gx2 * gx2 + gy2 * gy2 + 1e-8f);
            float lapl  = fabsf(4.0f * a11 - a01 - a10 - a12 - a21);

            // edge-clamped central differences (window indices proven in-range)
            const int x = bx0 + c0 + i;
            float dx = a12 - a10;                       // rc[i+2] - rc[i]
            if (x == 0)     dx = rc[3] - rc[1];
            if (x == W - 1) dx = rc[4] - rc[2];
            float dy = a21 - a01;                       // r1[i+1] - r0[i+1]
            if (y == 0)     dy = sg[ly + 2][lc + i] - sg[ly][lc + i];
            if (y == H - 1) dy = sg[ly][lc + i] - sg[ly - 2][lc + i];
            float gradm = sqrtf(dx * dx + dy * dy + 1e-8f);

            cc[i] = 0.5f * sobel + 0.3f * lapl + 0.2f * gradm;
            cmin = fminf(cmin, cc[i]);
            cmax = fmaxf(cmax, cc[i]);
        }
        float4 cv; cv.x = cc[0]; cv.y = cc[1]; cv.z = cc[2]; cv.w = cc[3];
        *(float4*)(g_contrast + b * HW + y * W + bx0 + c0) = cv;

#pragma unroll
        for (int s = 16; s > 0; s >>= 1) {
            cmin = fminf(cmin, __shfl_xor_sync(0xFFFFFFFFu, cmin, s));
            cmax = fmaxf(cmax, __shfl_xor_sync(0xFFFFFFFFu, cmax, s));
        }
        const int wid = lin >> 5;
        if ((lin & 31) == 0) { wmn[wid] = cmin; wmx[wid] = cmax; }
        __syncthreads();
        if (lin == 0) {
            float mn = wmn[0], mx = wmx[0];
#pragma unroll
            for (int s = 1; s < 8; ++s) {
                mn = fminf(mn, wmn[s]);
                mx = fmaxf(mx, wmx[s]);
            }
            g_bmn[cid] = mn;
            g_bmx[cid] = mx;
        }
    } else {
        // ---------------- threefry coords (img-independent, 1 cell/thread) -
        const int t = (bid >> 1) * 256 + lin;   // 0 .. 2M-1
        const int cell = t & (NCELL - 1);
        const int i = cell >> 9;
        const int j = cell & (TW - 1);

        float by = -1.0f + (float)i * (2.0f / 511.0f);
        float bx = -1.0f + (float)j * (2.0f / 511.0f);
        const float CELLSZ = 0.00390625f;   // 2/512 exact

        unsigned ctr = (unsigned)t * 8u;
        float u[8];
#pragma unroll
        for (int s = 0; s < 8; ++s) u[s] = tf_uniform(ctr + s);

        float4 c0, c1;
        c0.x = by + ((u[0] - 0.5f) * 0.8f) * CELLSZ;
        c0.y = bx + ((u[1] - 0.5f) * 0.8f) * CELLSZ;
        c0.z = by + ((u[2] - 0.5f) * 0.8f) * CELLSZ;
        c0.w = bx + ((u[3] - 0.5f) * 0.8f) * CELLSZ;
        c1.x = by + ((u[4] - 0.5f) * 0.8f) * CELLSZ;
        c1.y = bx + ((u[5] - 0.5f) * 0.8f) * CELLSZ;
        c1.z = by + ((u[6] - 0.5f) * 0.8f) * CELLSZ;
        c1.w = bx + ((u[7] - 0.5f) * 0.8f) * CELLSZ;

        float4* cp = (float4*)coords;
        cp[(size_t)t * 2]     = c0;
        cp[(size_t)t * 2 + 1] = c1;
    }
}

// ---------------------------------------------------------------------------
// horizontal 5-tap of zero-padded contrast at row y, cols x4..x4+3.
// ---------------------------------------------------------------------------
__device__ __forceinline__ float4 hconv(const float* __restrict__ cb,
                                        int y, int x4,
                                        float w0, float w1, float w2,
                                        float w3, float w4) {
    float4 r;
    if ((unsigned)y >= H) { r.x = r.y = r.z = r.w = 0.0f; return r; }
    const float* rp = cb + y * W + x4;
    float f0,f1,f2,f3,f4,f5,f6,f7;
    if (x4 >= 4) {
        float4 a = *(const float4*)(rp - 4);
        f0 = a.z; f1 = a.w;
    } else { f0 = f1 = 0.0f; }
    {
        float4 a = *(const float4*)rp;
        f2 = a.x; f3 = a.y; f4 = a.z; f5 = a.w;
    }
    if (x4 + 4 < W) {
        float4 a = *(const float4*)(rp + 4);
        f6 = a.x; f7 = a.y;
    } else { f6 = f7 = 0.0f; }
    r.x = w0*f0 + w1*f1 + w2*f2 + w3*f3 + w4*f4;
    r.y = w0*f1 + w1*f2 + w2*f3 + w3*f4 + w4*f5;
    r.z = w0*f2 + w1*f3 + w2*f4 + w3*f5 + w4*f6;
    r.w = w0*f3 + w1*f4 + w2*f5 + w3*f6 + w4*f7;
    return r;
}

// per-cell weights + ns==1 coords fixup (K1 wrote base+offset coords;
// launch boundary orders the writes).
__device__ __forceinline__ void do_cell(float d, int b, int i, int j,
                                        float* __restrict__ coords,
                                        float* __restrict__ weights) {
    int ns = (d > 0.7f) ? 4 : ((d > 0.4f) ? 2 : 1);
    float wv = d / (float)ns;
    int t = b * NCELL + i * TW + j;
    float4 w4;
    w4.x = wv;
    w4.y = (ns > 1) ? wv : 0.0f;
    w4.z = (ns > 3) ? wv : 0.0f;
    w4.w = (ns > 3) ? wv : 0.0f;
    ((float4*)weights)[t] = w4;
    if (ns == 1) {
        float by = -1.0f + (float)i * (2.0f / 511.0f);
        float bx = -1.0f + (float)j * (2.0f / 511.0f);
        float4 c0; c0.x = by; c0.y = bx; c0.z = by; c0.w = bx;
        float4* cp = (float4*)coords;
        cp[(size_t)t * 2]     = c0;
        cp[(size_t)t * 2 + 1] = c0;
    }
}

// ---------------------------------------------------------------------------
// K2: register-rolling separable gaussian + density + weights + fixup.
// Block (32,8) -> 128x64 tile (1024 blocks); thread owns 4 cols x 8 rows.
// launch_bounds forces <=64 regs -> 4 CTAs/SM.
// ---------------------------------------------------------------------------
__global__ void __launch_bounds__(256, 4)
k_main2(float* __restrict__ dens_out,
        float* __restrict__ coords,
        float* __restrict__ weights) {
    __shared__ float rmn[8], rmx[8];

    const int b   = blockIdx.z;
    const int bx0 = blockIdx.x * 128;
    const int by0 = blockIdx.y * 64;
    const int tx = threadIdx.x, ty = threadIdx.y;
    const int lin = ty * 32 + tx;

    // --- batch min/max from per-block results (exact: min/max associative)
    {
        float mn_ = 3.402823466e+38f, mx_ = 0.0f;
        for (int e = lin; e < CTILES; e += 256) {
            mn_ = fminf(mn_, g_bmn[b * CTILES + e]);
            mx_ = fmaxf(mx_, g_bmx[b * CTILES + e]);
        }
#pragma unroll
        for (int s = 16; s > 0; s >>= 1) {
            mn_ = fminf(mn_, __shfl_xor_sync(0xFFFFFFFFu, mn_, s));
            mx_ = fmaxf(mx_, __shfl_xor_sync(0xFFFFFFFFu, mx_, s));
        }
        if (tx == 0) { rmn[ty] = mn_; rmx[ty] = mx_; }
    }
    __syncthreads();
    float mn = rmn[0], mx = rmx[0];
#pragma unroll
    for (int s = 1; s < 8; ++s) {
        mn = fminf(mn, rmn[s]);
        mx = fmaxf(mx, rmx[s]);
    }
    const bool ok = mx > mn;
    const float inv = ok ? 1.0f / (mx - mn) : 0.0f;

    // gaussian weights (same fp path as reference)
    const float sg2 = (5.0f / 6.0f) * (5.0f / 6.0f);
    const float e1 = expf(-0.5f / sg2);
    const float e2 = expf(-2.0f / sg2);
    const float ksum = 1.0f + 2.0f * e1 + 2.0f * e2;
    float w[5];
    w[0] = e2 / ksum; w[1] = e1 / ksum; w[2] = 1.0f / ksum; w[3] = w[1]; w[4] = w[0];
    const float w0 = w[0], w1 = w[1], w2 = w[2], w3 = w[3], w4 = w[4];
    const float wsum = ((((w[0] + w[1]) + w[2]) + w[3]) + w[4]);

    const int x4 = bx0 + tx * 4;

    float wxv0 = 0.f, wxv1 = 0.f, wxv2 = 0.f, wxv3 = 0.f;
#pragma unroll
    for (int d = 0; d < 5; ++d) {
        if ((unsigned)(x4 + 0 + d - 2) < W) wxv0 += w[d];
        if ((unsigned)(x4 + 1 + d - 2) < W) wxv1 += w[d];
        if ((unsigned)(x4 + 2 + d - 2) < W) wxv2 += w[d];
        if ((unsigned)(x4 + 3 + d - 2) < W) wxv3 += w[d];
    }

    const float* cb = g_contrast + b * HW;
    const int ys = by0 + ty * 8;

    float4 h0 = hconv(cb, ys - 2, x4, w0, w1, w2, w3, w4);
    float4 h1 = hconv(cb, ys - 1, x4, w0, w1, w2, w3, w4);
    float4 h2 = hconv(cb, ys,     x4, w0, w1, w2, w3, w4);
    float4 h3 = hconv(cb, ys + 1, x4, w0, w1, w2, w3, w4);

    float* drow = dens_out + b * HW + ys * W + x4;

#pragma unroll
    for (int s = 0; s < 8; ++s) {
        const int y = ys + s;
        float4 h4 = hconv(cb, y + 2, x4, w0, w1, w2, w3, w4);

        float4 acc;
        acc.x = w0*h0.x + w1*h1.x + w2*h2.x + w3*h3.x + w4*h4.x;
        acc.y = w0*h0.y + w1*h1.y + w2*h2.y + w3*h3.y + w4*h4.y;
        acc.z = w0*h0.z + w1*h1.z + w2*h2.z + w3*h3.z + w4*h4.z;
        acc.w = w0*h0.w + w1*h1.w + w2*h2.w + w3*h3.w + w4*h4.w;

        float wyv = wsum;
        if (y < 2 || y >= H - 2) {
            wyv = 0.0f;
#pragma unroll
            for (int d = 0; d < 5; ++d)
                if ((unsigned)(y + d - 2) < H) wyv += w[d];
        }

        float4 dv;
        dv.x = 0.1f + 0.9f * sqrtf(fmaxf(inv * (acc.x - mn * (wyv * wxv0)), 0.0f));
        dv.y = 0.1f + 0.9f * sqrtf(fmaxf(inv * (acc.y - mn * (wyv * wxv1)), 0.0f));
        dv.z = 0.1f + 0.9f * sqrtf(fmaxf(inv * (acc.z - mn * (wyv * wxv2)), 0.0f));
        dv.w = 0.1f + 0.9f * sqrtf(fmaxf(inv * (acc.w - mn * (wyv * wxv3)), 0.0f));

        *(float4*)drow = dv;
        drow += W;

        if ((y & 1) == 0) {
            const int i = y >> 1;
            const int j0 = x4 >> 1;
            do_cell(dv.x, b, i, j0,     coords, weights);
            do_cell(dv.z, b, i, j0 + 1, coords, weights);
        }

        h0 = h1; h1 = h2; h2 = h3; h3 = h4;
    }
}

// ---------------------------------------------------------------------------
extern "C" void kernel_launch(void* const* d_in, const int* in_sizes, int n_in,
                              void* d_out, int out_size) {
    const float* img = (const float*)d_in[0];
    float* out = (float*)d_out;
    float* coords  = out;
    float* weights = out + COORDS_ELEMS;
    float* dens    = out + COORDS_ELEMS + WEIGHTS_ELEMS;

    k_main1<<<2 * NCONTRAST, 256>>>(img, coords);
    {
        dim3 grid(W / 128, H / 64, BATCH), block(32, 8);
        k_main2<<<grid, block>>>(dens, coords, weights);
    }
}